// round 15
// baseline (speedup 1.0000x reference)
#include <cuda_runtime.h>
#include <cstdint>
#include <cstddef>

#define BB 8
#define TT 128
#define SS 512
#define DD 128
#define CL 8           // cluster size (CTAs per batch)
#define ROWS 64        // SS/CL encoder rows per CTA
#define NTH 512
#define COLS_PER 16    // DD/CL output columns per CTA

// scratch (static device globals -- no allocation)
__device__ float g_HU[BB * SS * DD];          // H @ Ua
__device__ float g_XW4[BB * TT * 4 * DD];     // x @ {Wi,Wf,Wc,Wo} + bias

// ---------------------------------------------------------------- helpers
__device__ __forceinline__ uint32_t s2u(const void* p) {
    uint32_t a;
    asm("{ .reg .u64 t; cvta.to.shared.u64 t, %1; cvt.u32.u64 %0, t; }"
        : "=r"(a) : "l"(p));
    return a;
}
__device__ __forceinline__ void st_rank(uint32_t laddr, uint32_t rank, float v) {
    uint32_t r;
    asm("mapa.shared::cluster.u32 %0, %1, %2;" : "=r"(r) : "r"(laddr), "r"(rank));
    asm volatile("st.shared::cluster.f32 [%0], %1;" :: "r"(r), "f"(v) : "memory");
}
#define CLUSTER_SYNC() do { \
    asm volatile("barrier.cluster.arrive.aligned;" ::: "memory"); \
    asm volatile("barrier.cluster.wait.aligned;"   ::: "memory"); \
} while (0)

// ---- mbarrier handshake (fan-in via __syncthreads, single release-arrive
// per peer, single-thread acquire-wait + __syncthreads fan-out) ----
__device__ __forceinline__ void mbar_init(uint32_t bar, uint32_t cnt) {
    asm volatile("mbarrier.init.shared.b64 [%0], %1;" :: "r"(bar), "r"(cnt) : "memory");
}
// cluster-scope release fence, then one arrive on peer `rank`'s barrier.
__device__ __forceinline__ void mbar_arrive_rank(uint32_t lbar, uint32_t rank) {
    uint32_t r;
    asm("mapa.shared::cluster.u32 %0, %1, %2;" : "=r"(r) : "r"(lbar), "r"(rank));
    asm volatile("fence.acq_rel.cluster;" ::: "memory");
    asm volatile("mbarrier.arrive.shared::cluster.b64 _, [%0];" :: "r"(r) : "memory");
}
__device__ __forceinline__ void mbar_wait(uint32_t bar, uint32_t parity) {
    asm volatile(
        "{\n\t"
        ".reg .pred P1;\n\t"
        "LAB_WAIT_%=:\n\t"
        "mbarrier.try_wait.parity.acquire.cluster.shared::cta.b64 P1, [%0], %1, 0x989680;\n\t"
        "@P1 bra LAB_DONE_%=;\n\t"
        "bra LAB_WAIT_%=;\n\t"
        "LAB_DONE_%=:\n\t"
        "}"
        :: "r"(bar), "r"(parity) : "memory");
}

// MUFU tanh for the attention score path (feeds softmax weights only;
// measured rel_err impact: none). Runs on the otherwise-idle MUFU pipe.
__device__ __forceinline__ float tanh_mufu(float x) {
    float y;
    asm("tanh.approx.f32 %0, %1;" : "=f"(y) : "f"(x));
    return y;
}
// accurate activations for the LSTM gates (recurrent state path)
__device__ __forceinline__ float sigmoid_acc(float x) {
    return __fdividef(1.0f, 1.0f + __expf(-x));
}
__device__ __forceinline__ float tanh_acc(float x) {
    float e = __expf(2.0f * x);
    return __fdividef(e - 1.0f, e + 1.0f);
}

// ---------------------------------------------------------------- precompute
// HU[b,s,:] = H[b,s,:] @ Ua      (8 rows per block)
__global__ void __launch_bounds__(DD) hu_kernel(const float* __restrict__ Hm,
                                                const float* __restrict__ Ua) {
    __shared__ float hrow[8][DD];
    int r0 = blockIdx.x * 8;
    int d = threadIdx.x;
    #pragma unroll
    for (int i = 0; i < 8; i++) hrow[i][d] = Hm[(size_t)(r0 + i) * DD + d];
    __syncthreads();
    float acc[8];
    #pragma unroll
    for (int i = 0; i < 8; i++) acc[i] = 0.0f;
    #pragma unroll 4
    for (int k = 0; k < DD; k++) {
        float u = Ua[k * DD + d];
        #pragma unroll
        for (int i = 0; i < 8; i++) acc[i] = fmaf(hrow[i][k], u, acc[i]);
    }
    #pragma unroll
    for (int i = 0; i < 8; i++) g_HU[(size_t)(r0 + i) * DD + d] = acc[i];
}

// XW4[row,g,:] = x[row,:] @ W_g + b_g   (8 rows per block)
__global__ void __launch_bounds__(DD) xw_kernel(const float* __restrict__ x,
    const float* __restrict__ Wi_, const float* __restrict__ Wf_,
    const float* __restrict__ Wc_, const float* __restrict__ Wo_,
    const float* __restrict__ bi_, const float* __restrict__ bf_,
    const float* __restrict__ bc_, const float* __restrict__ bo_) {
    __shared__ float xr[8][DD];
    int r0 = blockIdx.x * 8;
    int d = threadIdx.x;
    #pragma unroll
    for (int i = 0; i < 8; i++) xr[i][d] = x[(size_t)(r0 + i) * DD + d];
    __syncthreads();
    const float* Ws[4] = {Wi_, Wf_, Wc_, Wo_};
    const float* bs[4] = {bi_, bf_, bc_, bo_};
    #pragma unroll
    for (int g = 0; g < 4; g++) {
        float bb = bs[g][d];
        float acc[8];
        #pragma unroll
        for (int i = 0; i < 8; i++) acc[i] = bb;
        #pragma unroll 4
        for (int k = 0; k < DD; k++) {
            float w = Ws[g][k * DD + d];
            #pragma unroll
            for (int i = 0; i < 8; i++) acc[i] = fmaf(xr[i][k], w, acc[i]);
        }
        #pragma unroll
        for (int i = 0; i < 8; i++)
            g_XW4[(((size_t)(r0 + i)) * 4 + g) * DD + d] = acc[i];
    }
}

// ---------------------------------------------------------------- main persistent kernel
// grid (CL, BB): cluster of CL CTAs along x per batch (blockIdx.y).
__global__ void __launch_bounds__(NTH, 1) __cluster_dims__(CL, 1, 1)
attn_lstm_kernel(const float* __restrict__ H, const float* __restrict__ init_states,
                 const float* __restrict__ Wa, const float* __restrict__ v,
                 const float* __restrict__ Ui, const float* __restrict__ Uf,
                 const float* __restrict__ Uc, const float* __restrict__ Uo,
                 const float* __restrict__ Ci, const float* __restrict__ Cf,
                 const float* __restrict__ Cc, const float* __restrict__ Co,
                 float* __restrict__ out)
{
    __shared__ float Wa_s[COLS_PER][DD];     // Wa rows [16r, 16r+16)
    __shared__ float v_s[DD];
    __shared__ float hbuf[2][DD];
    __shared__ float2 qv2_s[DD];             // (q[d], v[d]) pairs for phase 2
    __shared__ float qpart[CL][DD];
    __shared__ float2 hc_s[DD];              // (h[k], ctx[k]) pairs for phase 3
    __shared__ float ctxpart[CL][DD + 4];    // [.., DD] = partial exp-sum
    __shared__ float wred[16][DD];
    __shared__ float wsum[16];
    __shared__ float gate_sm[4][COLS_PER];
    __shared__ float hn[COLS_PER];
    __shared__ alignas(8) unsigned long long mbarA, mbarB;

    const int tid  = threadIdx.x;
    const int b    = blockIdx.y;
    uint32_t rank;
    asm("mov.u32 %0, %%cluster_ctarank;" : "=r"(rank));
    const int j    = tid & 7;
    const int sl   = tid >> 3;           // row-local (phase2) / pair index (phase3)
    const int warp = tid >> 5;
    const int lane = tid & 31;

    const int g   = sl >> 4;             // gate 0..3  (i, f, c~, o)
    const int cl_ = sl & 15;             // local column
    const int col = (int)rank * COLS_PER + cl_;

    const uint32_t bA = s2u((const void*)&mbarA);
    const uint32_t bB = s2u((const void*)&mbarB);

    // ---- persistent register tiles ----
    float HUr[16], Hr[16], Ur[16], Cr[16];
    {
        const int srow = (int)rank * ROWS + sl;
        const float* hu = g_HU + ((size_t)b * SS + srow) * DD;
        const float* hp = H    + ((size_t)b * SS + srow) * DD;
        #pragma unroll
        for (int m = 0; m < 16; m++) { int d = j + 8 * m; HUr[m] = hu[d]; Hr[m] = hp[d]; }
        const float* Ug = (g == 0) ? Ui : (g == 1) ? Uf : (g == 2) ? Uc : Uo;
        const float* Cg = (g == 0) ? Ci : (g == 1) ? Cf : (g == 2) ? Cc : Co;
        #pragma unroll
        for (int m = 0; m < 16; m++) { int k = j + 8 * m; Ur[m] = Ug[k * DD + col]; Cr[m] = Cg[k * DD + col]; }
    }
    // c state is private to its owning thread: register, never broadcast
    float creg = (tid < COLS_PER)
               ? init_states[(BB + b) * DD + (int)rank * COLS_PER + tid] : 0.0f;

    // ---- smem init ----
    for (int i = tid; i < COLS_PER * DD; i += NTH) {
        int kr = i >> 7, dd = i & 127;
        Wa_s[kr][dd] = Wa[((int)rank * COLS_PER + kr) * DD + dd];
    }
    float vreg = 0.0f;
    if (tid < DD) {
        vreg         = v[tid];
        v_s[tid]     = vreg;
        hbuf[0][tid] = init_states[b * DD + tid];
        hbuf[1][tid] = 0.0f;
    }
    if (tid == 0) { mbar_init(bA, CL); mbar_init(bB, CL); }
    __syncthreads();
    CLUSTER_SYNC();                       // peers' mbarriers live before any arrives

    // initial q partial from h0's k-slice, broadcast to all CTAs (incl. self)
    if (tid < DD) {
        float acc = 0.0f;
        #pragma unroll
        for (int k = 0; k < COLS_PER; k++)
            acc = fmaf(hbuf[0][(int)rank * COLS_PER + k], Wa_s[k][tid], acc);
        uint32_t la = s2u(&qpart[rank][tid]);
        #pragma unroll
        for (int rr = 0; rr < CL; rr++) st_rank(la, (uint32_t)rr, acc);
    }
    __syncthreads();
    if (tid < CL) mbar_arrive_rank(bA, (uint32_t)tid);

    const float* xw_base = g_XW4 + (size_t)b * TT * 4 * DD;
    uint32_t phA = 0, phB = 0;

    for (int t = 0; t < TT; t++) {
        const int p = t & 1;
        // ---- barrier A: qpart + hbuf[p] from all peers visible ----
        if (tid == 0) mbar_wait(bA, phA);
        phA ^= 1;
        __syncthreads();

        // prefetch the x@W gate term (L2 latency hidden behind phase 2)
        float xwv = (j == 0) ? xw_base[((size_t)t * 4 + g) * DD + col] : 0.0f;

        // ---- build full q, fused with v into float2 pairs ----
        if (tid < DD) {
            float acc = qpart[0][tid];
            #pragma unroll
            for (int rr = 1; rr < CL; rr++) acc += qpart[rr][tid];
            qv2_s[tid] = make_float2(acc, vreg);
        }
        __syncthreads();

        // ---- phase 2: scores + exp + local context partial for 64 rows ----
        {
            float acc = 0.0f;
            #pragma unroll
            for (int m = 0; m < 16; m++) {
                float2 qv = qv2_s[j + 8 * m];      // one LDS.64: (q, v)
                acc = fmaf(tanh_mufu(HUr[m] + qv.x), qv.y, acc);
            }
            acc += __shfl_xor_sync(0xffffffffu, acc, 1);
            acc += __shfl_xor_sync(0xffffffffu, acc, 2);
            acc += __shfl_xor_sync(0xffffffffu, acc, 4);
            float e = __expf(acc);           // scores are tiny; no max-shift needed
            float cp[16];
            #pragma unroll
            for (int m = 0; m < 16; m++) cp[m] = e * Hr[m];
            #pragma unroll
            for (int m = 0; m < 16; m++) {   // reduce over the 4 rows in this warp
                cp[m] += __shfl_xor_sync(0xffffffffu, cp[m], 8);
                cp[m] += __shfl_xor_sync(0xffffffffu, cp[m], 16);
            }
            float es = e + __shfl_xor_sync(0xffffffffu, e, 8);
            es += __shfl_xor_sync(0xffffffffu, es, 16);
            if (lane < 8) {
                #pragma unroll
                for (int m = 0; m < 16; m++) wred[warp][lane + 8 * m] = cp[m];
                if (lane == 0) wsum[warp] = es;
            }
        }
        __syncthreads();
        // local reduce over 16 warps, broadcast (ctx partial + exp-sum) to all CTAs
        if (tid < DD) {
            float acc = wred[0][tid];
            #pragma unroll
            for (int w = 1; w < 16; w++) acc += wred[w][tid];
            uint32_t la = s2u(&ctxpart[rank][tid]);
            #pragma unroll
            for (int rr = 0; rr < CL; rr++) st_rank(la, (uint32_t)rr, acc);
            if (tid == 0) {
                float es = wsum[0];
                #pragma unroll
                for (int w = 1; w < 16; w++) es += wsum[w];
                uint32_t lb = s2u(&ctxpart[rank][DD]);
                #pragma unroll
                for (int rr = 0; rr < CL; rr++) st_rank(lb, (uint32_t)rr, es);
            }
        }
        __syncthreads();
        if (tid < CL) mbar_arrive_rank(bB, (uint32_t)tid);
        // ---- barrier B: ctx partials from all peers visible ----
        if (tid == 0) mbar_wait(bB, phB);
        phB ^= 1;
        __syncthreads();

        // ---- phase 3: full context fused with h into float2 pairs ----
        if (tid < DD) {
            float acc = ctxpart[0][tid];
            float es  = ctxpart[0][DD];
            #pragma unroll
            for (int rr = 1; rr < CL; rr++) { acc += ctxpart[rr][tid]; es += ctxpart[rr][DD]; }
            hc_s[tid] = make_float2(hbuf[p][tid], acc * __fdividef(1.0f, es));
        }
        __syncthreads();
        {
            float acc = 0.0f;
            #pragma unroll
            for (int m = 0; m < 16; m++) {
                float2 hc = hc_s[j + 8 * m];       // one LDS.64: (h, ctx)
                acc = fmaf(hc.x, Ur[m], acc);
                acc = fmaf(hc.y, Cr[m], acc);
            }
            acc += __shfl_xor_sync(0xffffffffu, acc, 1);
            acc += __shfl_xor_sync(0xffffffffu, acc, 2);
            acc += __shfl_xor_sync(0xffffffffu, acc, 4);
            if (j == 0) {
                float pre = acc + xwv;
                gate_sm[g][cl_] = (g == 2) ? tanh_acc(pre) : sigmoid_acc(pre);
            }
        }
        __syncthreads();
        if (tid < COLS_PER) {
            float ig = gate_sm[0][tid], fg = gate_sm[1][tid];
            float gg = gate_sm[2][tid], og = gate_sm[3][tid];
            int colw = (int)rank * COLS_PER + tid;
            float cnew = fmaf(fg, creg, ig * gg);
            creg = cnew;
            float hnew = og * tanh_acc(cnew);
            hn[tid] = hnew;
            out[((size_t)b * TT + t) * DD + colw] = hnew;
            if (t < TT - 1) {
                uint32_t lah = s2u(&hbuf[p ^ 1][colw]);
                #pragma unroll
                for (int rr = 0; rr < CL; rr++) st_rank(lah, (uint32_t)rr, hnew);
            }
        }
        __syncthreads();
        // next-step q partial from this CTA's h-slice
        if (t < TT - 1) {
            if (tid < DD) {
                float acc = 0.0f;
                #pragma unroll
                for (int k = 0; k < COLS_PER; k++) acc = fmaf(hn[k], Wa_s[k][tid], acc);
                uint32_t la = s2u(&qpart[rank][tid]);
                #pragma unroll
                for (int rr = 0; rr < CL; rr++) st_rank(la, (uint32_t)rr, acc);
            }
            __syncthreads();
            if (tid < CL) mbar_arrive_rank(bA, (uint32_t)tid);
        }
    }
    CLUSTER_SYNC();                       // no CTA exits with peer DSMEM traffic in flight
}

// ---------------------------------------------------------------- launch
extern "C" void kernel_launch(void* const* d_in, const int* in_sizes, int n_in,
                              void* d_out, int out_size) {
    (void)in_sizes; (void)n_in; (void)out_size;
    const float* x    = (const float*)d_in[0];
    const float* H    = (const float*)d_in[1];
    const float* init = (const float*)d_in[2];
    const float* Wa   = (const float*)d_in[3];
    const float* Ua   = (const float*)d_in[4];
    const float* v    = (const float*)d_in[5];
    const float* Wi   = (const float*)d_in[6];
    const float* Ui   = (const float*)d_in[7];
    const float* Ci   = (const float*)d_in[8];
    const float* bi   = (const float*)d_in[9];
    const float* Wf   = (const float*)d_in[10];
    const float* Uf   = (const float*)d_in[11];
    const float* Cf   = (const float*)d_in[12];
    const float* bf   = (const float*)d_in[13];
    const float* Wc   = (const float*)d_in[14];
    const float* Uc   = (const float*)d_in[15];
    const float* Cc   = (const float*)d_in[16];
    const float* bc   = (const float*)d_in[17];
    const float* Wo   = (const float*)d_in[18];
    const float* Uo   = (const float*)d_in[19];
    const float* Co   = (const float*)d_in[20];
    const float* bo   = (const float*)d_in[21];
    float* out = (float*)d_out;

    hu_kernel<<<(BB * SS) / 8, DD>>>(H, Ua);
    xw_kernel<<<(BB * TT) / 8, DD>>>(x, Wi, Wf, Wc, Wo, bi, bf, bc, bo);
    attn_lstm_kernel<<<dim3(CL, BB), NTH>>>(H, init, Wa, v,
                                            Ui, Uf, Uc, Uo, Ci, Cf, Cc, Co, out);
}

// round 16
// speedup vs baseline: 1.0453x; 1.0453x over previous
#include <cuda_runtime.h>
#include <cstdint>
#include <cstddef>

#define BB 8
#define TT 128
#define SS 512
#define DD 128
#define CL 8           // cluster size (CTAs per batch)
#define ROWS 64        // SS/CL encoder rows per CTA
#define NTH 512
#define COLS_PER 16    // DD/CL output columns per CTA

// scratch (static device globals -- no allocation)
__device__ float g_HU[BB * SS * DD];          // H @ Ua
__device__ float g_XW4[BB * TT * 4 * DD];     // x @ {Wi,Wf,Wc,Wo} + bias

// ---------------------------------------------------------------- helpers
__device__ __forceinline__ uint32_t s2u(const void* p) {
    uint32_t a;
    asm("{ .reg .u64 t; cvta.to.shared.u64 t, %1; cvt.u32.u64 %0, t; }"
        : "=r"(a) : "l"(p));
    return a;
}
__device__ __forceinline__ void st_rank(uint32_t laddr, uint32_t rank, float v) {
    uint32_t r;
    asm("mapa.shared::cluster.u32 %0, %1, %2;" : "=r"(r) : "r"(laddr), "r"(rank));
    asm volatile("st.shared::cluster.f32 [%0], %1;" :: "r"(r), "f"(v) : "memory");
}
#define CLUSTER_ARRIVE() \
    asm volatile("barrier.cluster.arrive.aligned;" ::: "memory")
#define CLUSTER_WAIT() \
    asm volatile("barrier.cluster.wait.aligned;"   ::: "memory")
#define CLUSTER_SYNC() do { CLUSTER_ARRIVE(); CLUSTER_WAIT(); } while (0)

// MUFU tanh for the attention score path (feeds softmax weights only;
// measured rel_err impact: none). Runs on the otherwise-idle MUFU pipe.
__device__ __forceinline__ float tanh_mufu(float x) {
    float y;
    asm("tanh.approx.f32 %0, %1;" : "=f"(y) : "f"(x));
    return y;
}
// accurate activations for the LSTM gates (recurrent state path)
__device__ __forceinline__ float sigmoid_acc(float x) {
    return __fdividef(1.0f, 1.0f + __expf(-x));
}
__device__ __forceinline__ float tanh_acc(float x) {
    float e = __expf(2.0f * x);
    return __fdividef(e - 1.0f, e + 1.0f);
}

// ---------------------------------------------------------------- precompute
// HU[b,s,:] = H[b,s,:] @ Ua      (8 rows per block)
__global__ void __launch_bounds__(DD) hu_kernel(const float* __restrict__ Hm,
                                                const float* __restrict__ Ua) {
    __shared__ float hrow[8][DD];
    int r0 = blockIdx.x * 8;
    int d = threadIdx.x;
    #pragma unroll
    for (int i = 0; i < 8; i++) hrow[i][d] = Hm[(size_t)(r0 + i) * DD + d];
    __syncthreads();
    float acc[8];
    #pragma unroll
    for (int i = 0; i < 8; i++) acc[i] = 0.0f;
    #pragma unroll 4
    for (int k = 0; k < DD; k++) {
        float u = Ua[k * DD + d];
        #pragma unroll
        for (int i = 0; i < 8; i++) acc[i] = fmaf(hrow[i][k], u, acc[i]);
    }
    #pragma unroll
    for (int i = 0; i < 8; i++) g_HU[(size_t)(r0 + i) * DD + d] = acc[i];
}

// XW4[row,g,:] = x[row,:] @ W_g + b_g   (8 rows per block)
__global__ void __launch_bounds__(DD) xw_kernel(const float* __restrict__ x,
    const float* __restrict__ Wi_, const float* __restrict__ Wf_,
    const float* __restrict__ Wc_, const float* __restrict__ Wo_,
    const float* __restrict__ bi_, const float* __restrict__ bf_,
    const float* __restrict__ bc_, const float* __restrict__ bo_) {
    __shared__ float xr[8][DD];
    int r0 = blockIdx.x * 8;
    int d = threadIdx.x;
    #pragma unroll
    for (int i = 0; i < 8; i++) xr[i][d] = x[(size_t)(r0 + i) * DD + d];
    __syncthreads();
    const float* Ws[4] = {Wi_, Wf_, Wc_, Wo_};
    const float* bs[4] = {bi_, bf_, bc_, bo_};
    #pragma unroll
    for (int g = 0; g < 4; g++) {
        float bb = bs[g][d];
        float acc[8];
        #pragma unroll
        for (int i = 0; i < 8; i++) acc[i] = bb;
        #pragma unroll 4
        for (int k = 0; k < DD; k++) {
            float w = Ws[g][k * DD + d];
            #pragma unroll
            for (int i = 0; i < 8; i++) acc[i] = fmaf(xr[i][k], w, acc[i]);
        }
        #pragma unroll
        for (int i = 0; i < 8; i++)
            g_XW4[(((size_t)(r0 + i)) * 4 + g) * DD + d] = acc[i];
    }
}

// ---------------------------------------------------------------- main persistent kernel
// grid (CL, BB): cluster of CL CTAs along x per batch (blockIdx.y).
__global__ void __launch_bounds__(NTH, 1) __cluster_dims__(CL, 1, 1)
attn_lstm_kernel(const float* __restrict__ H, const float* __restrict__ init_states,
                 const float* __restrict__ Wa, const float* __restrict__ v,
                 const float* __restrict__ Ui, const float* __restrict__ Uf,
                 const float* __restrict__ Uc, const float* __restrict__ Uo,
                 const float* __restrict__ Ci, const float* __restrict__ Cf,
                 const float* __restrict__ Cc, const float* __restrict__ Co,
                 float* __restrict__ out)
{
    __shared__ float Wa_s[COLS_PER][DD];     // Wa rows [16r, 16r+16)
    __shared__ float v_s[DD];
    __shared__ float hbuf[2][DD];
    __shared__ float2 qv2_s[DD];             // (q[d], v[d]) pairs for phase 2
    __shared__ float qpart[CL][DD];
    __shared__ float ctx_s[DD];
    __shared__ float ctxpart[CL][DD + 4];    // [.., DD] = partial exp-sum
    __shared__ float wred[16][DD];
    __shared__ float wsum[16];
    __shared__ float hn[COLS_PER];

    const int tid  = threadIdx.x;
    const int b    = blockIdx.y;
    uint32_t rank;
    asm("mov.u32 %0, %%cluster_ctarank;" : "=r"(rank));
    const int j    = tid & 7;
    const int sl   = tid >> 3;           // row-local (phase2) / (col,gate) index (phase3)
    const int warp = tid >> 5;
    const int lane = tid & 31;

    // phase-3 mapping: all 4 gates of a column live in ONE warp.
    // sl = cl*4 + g  =>  j==0 reducer lanes are {0,8,16,24} of warp cl.
    const int g   = sl & 3;              // gate 0..3  (i, f, c~, o)
    const int cl_ = sl >> 2;             // local column == warp for j==0 threads
    const int col = (int)rank * COLS_PER + cl_;

    // ---- persistent register tiles ----
    float HUr[16], Hr[16], Ur[16], Cr[16];
    {
        const int srow = (int)rank * ROWS + sl;
        const float* hu = g_HU + ((size_t)b * SS + srow) * DD;
        const float* hp = H    + ((size_t)b * SS + srow) * DD;
        #pragma unroll
        for (int m = 0; m < 16; m++) { int d = j + 8 * m; HUr[m] = hu[d]; Hr[m] = hp[d]; }
        const float* Ug = (g == 0) ? Ui : (g == 1) ? Uf : (g == 2) ? Uc : Uo;
        const float* Cg = (g == 0) ? Ci : (g == 1) ? Cf : (g == 2) ? Cc : Co;
        #pragma unroll
        for (int m = 0; m < 16; m++) { int k = j + 8 * m; Ur[m] = Ug[k * DD + col]; Cr[m] = Cg[k * DD + col]; }
    }
    // c state: lane 0 of warp `cl` owns column rank*16+cl
    float creg = (lane == 0)
               ? init_states[(BB + b) * DD + (int)rank * COLS_PER + warp] : 0.0f;

    // ---- smem init ----
    for (int i = tid; i < COLS_PER * DD; i += NTH) {
        int kr = i >> 7, dd = i & 127;
        Wa_s[kr][dd] = Wa[((int)rank * COLS_PER + kr) * DD + dd];
    }
    float vreg = 0.0f;
    if (tid < DD) {
        vreg         = v[tid];
        v_s[tid]     = vreg;
        hbuf[0][tid] = init_states[b * DD + tid];
        hbuf[1][tid] = 0.0f;
    }
    __syncthreads();
    // initial q partial from h0's k-slice, broadcast to all CTAs (incl. self)
    if (tid < DD) {
        float acc = 0.0f;
        #pragma unroll
        for (int k = 0; k < COLS_PER; k++)
            acc = fmaf(hbuf[0][(int)rank * COLS_PER + k], Wa_s[k][tid], acc);
        uint32_t la = s2u(&qpart[rank][tid]);
        #pragma unroll
        for (int rr = 0; rr < CL; rr++) st_rank(la, (uint32_t)rr, acc);
    }

    const float* xw_base = g_XW4 + (size_t)b * TT * 4 * DD;
    const bool is_gate_ld = (j == 0);    // lanes {0,8,16,24} of each warp

    CLUSTER_ARRIVE();
    CLUSTER_WAIT();                      // initial qpart + hbuf[0] visible

    for (int t = 0; t < TT; t++) {
        const int p = t & 1;

        // prefetch the x@W gate term (issued in barrier-A slack at loop tail;
        // first iteration issues it here)
        float xwv = is_gate_ld ? xw_base[((size_t)t * 4 + g) * DD + col] : 0.0f;

        // ---- build full q, fused with v into float2 pairs ----
        if (tid < DD) {
            float acc = qpart[0][tid];
            #pragma unroll
            for (int rr = 1; rr < CL; rr++) acc += qpart[rr][tid];
            qv2_s[tid] = make_float2(acc, vreg);
        }
        __syncthreads();                 // (#1)

        // ---- phase 2: scores + exp + local context partial for 64 rows ----
        {
            float acc = 0.0f;
            #pragma unroll
            for (int m = 0; m < 16; m++) {
                float2 qv = qv2_s[j + 8 * m];      // one LDS.64: (q, v)
                acc = fmaf(tanh_mufu(HUr[m] + qv.x), qv.y, acc);
            }
            acc += __shfl_xor_sync(0xffffffffu, acc, 1);
            acc += __shfl_xor_sync(0xffffffffu, acc, 2);
            acc += __shfl_xor_sync(0xffffffffu, acc, 4);
            float e = __expf(acc);           // scores are tiny; no max-shift needed
            float cp[16];
            #pragma unroll
            for (int m = 0; m < 16; m++) cp[m] = e * Hr[m];
            #pragma unroll
            for (int m = 0; m < 16; m++) {   // reduce over the 4 rows in this warp
                cp[m] += __shfl_xor_sync(0xffffffffu, cp[m], 8);
                cp[m] += __shfl_xor_sync(0xffffffffu, cp[m], 16);
            }
            float es = e + __shfl_xor_sync(0xffffffffu, e, 8);
            es += __shfl_xor_sync(0xffffffffu, es, 16);
            if (lane < 8) {
                #pragma unroll
                for (int m = 0; m < 16; m++) wred[warp][lane + 8 * m] = cp[m];
                if (lane == 0) wsum[warp] = es;
            }
        }
        __syncthreads();                 // (#2)
        // local reduce over 16 warps, broadcast (ctx partial + exp-sum) to all CTAs
        if (tid < DD) {
            float acc = wred[0][tid];
            #pragma unroll
            for (int w = 1; w < 16; w++) acc += wred[w][tid];
            uint32_t la = s2u(&ctxpart[rank][tid]);
            #pragma unroll
            for (int rr = 0; rr < CL; rr++) st_rank(la, (uint32_t)rr, acc);
            if (tid == 0) {
                float es = wsum[0];
                #pragma unroll
                for (int w = 1; w < 16; w++) es += wsum[w];
                uint32_t lb = s2u(&ctxpart[rank][DD]);
                #pragma unroll
                for (int rr = 0; rr < CL; rr++) st_rank(lb, (uint32_t)rr, es);
            }
        }
        CLUSTER_ARRIVE();                // barrier B arrive (stores ordered per-thread)

        // ---- overlap with barrier-B wait: h·U part of the gate dot ----
        float acc_h = 0.0f;
        #pragma unroll
        for (int m = 0; m < 16; m++)
            acc_h = fmaf(hbuf[p][j + 8 * m], Ur[m], acc_h);

        CLUSTER_WAIT();                  // ctx partials from all peers visible

        // ---- phase 3: full context ----
        if (tid < DD) {
            float acc = ctxpart[0][tid];
            float es  = ctxpart[0][DD];
            #pragma unroll
            for (int rr = 1; rr < CL; rr++) { acc += ctxpart[rr][tid]; es += ctxpart[rr][DD]; }
            ctx_s[tid] = acc * __fdividef(1.0f, es);
        }
        __syncthreads();                 // (#3)
        // gate dot (ctx part) + warp-local gate combine + state update
        {
            float acc = acc_h;
            #pragma unroll
            for (int m = 0; m < 16; m++)
                acc = fmaf(ctx_s[j + 8 * m], Cr[m], acc);
            acc += __shfl_xor_sync(0xffffffffu, acc, 1);
            acc += __shfl_xor_sync(0xffffffffu, acc, 2);
            acc += __shfl_xor_sync(0xffffffffu, acc, 4);
            float pre = acc + xwv;       // valid at lanes {0,8,16,24}
            float act = (g == 2) ? tanh_acc(pre) : sigmoid_acc(pre);
            // gather the 4 gates of this warp's column
            float ig = __shfl_sync(0xffffffffu, act, 0);
            float fg = __shfl_sync(0xffffffffu, act, 8);
            float gg = __shfl_sync(0xffffffffu, act, 16);
            float og = __shfl_sync(0xffffffffu, act, 24);
            if (lane == 0) {
                int colw = (int)rank * COLS_PER + warp;
                float cnew = fmaf(fg, creg, ig * gg);
                creg = cnew;
                float hnew = og * tanh_acc(cnew);
                hn[warp] = hnew;
                out[((size_t)b * TT + t) * DD + colw] = hnew;
                if (t < TT - 1) {
                    uint32_t lah = s2u(&hbuf[p ^ 1][colw]);
                    #pragma unroll
                    for (int rr = 0; rr < CL; rr++) st_rank(lah, (uint32_t)rr, hnew);
                }
            }
        }
        __syncthreads();                 // (#4) hn visible
        if (t < TT - 1) {
            // next-step q partial from this CTA's h-slice
            if (tid < DD) {
                float acc = 0.0f;
                #pragma unroll
                for (int k = 0; k < COLS_PER; k++) acc = fmaf(hn[k], Wa_s[k][tid], acc);
                uint32_t la = s2u(&qpart[rank][tid]);
                #pragma unroll
                for (int rr = 0; rr < CL; rr++) st_rank(la, (uint32_t)rr, acc);
            }
            CLUSTER_ARRIVE();            // barrier A arrive
            CLUSTER_WAIT();
        }
    }
    CLUSTER_SYNC();                      // no CTA exits with peer DSMEM traffic in flight
}

// ---------------------------------------------------------------- launch
extern "C" void kernel_launch(void* const* d_in, const int* in_sizes, int n_in,
                              void* d_out, int out_size) {
    (void)in_sizes; (void)n_in; (void)out_size;
    const float* x    = (const float*)d_in[0];
    const float* H    = (const float*)d_in[1];
    const float* init = (const float*)d_in[2];
    const float* Wa   = (const float*)d_in[3];
    const float* Ua   = (const float*)d_in[4];
    const float* v    = (const float*)d_in[5];
    const float* Wi   = (const float*)d_in[6];
    const float* Ui   = (const float*)d_in[7];
    const float* Ci   = (const float*)d_in[8];
    const float* bi   = (const float*)d_in[9];
    const float* Wf   = (const float*)d_in[10];
    const float* Uf   = (const float*)d_in[11];
    const float* Cf   = (const float*)d_in[12];
    const float* bf   = (const float*)d_in[13];
    const float* Wc   = (const float*)d_in[14];
    const float* Uc   = (const float*)d_in[15];
    const float* Cc   = (const float*)d_in[16];
    const float* bc   = (const float*)d_in[17];
    const float* Wo   = (const float*)d_in[18];
    const float* Uo   = (const float*)d_in[19];
    const float* Co   = (const float*)d_in[20];
    const float* bo   = (const float*)d_in[21];
    float* out = (float*)d_out;

    hu_kernel<<<(BB * SS) / 8, DD>>>(H, Ua);
    xw_kernel<<<(BB * TT) / 8, DD>>>(x, Wi, Wf, Wc, Wo, bi, bf, bc, bo);
    attn_lstm_kernel<<<dim3(CL, BB), NTH>>>(H, init, Wa, v,
                                            Ui, Uf, Uc, Uo, Ci, Cf, Cc, Co, out);
}